// round 6
// baseline (speedup 1.0000x reference)
#include <cuda_runtime.h>
#include <cuda_fp16.h>
#include <cstdint>

// ============================ problem constants ============================
#define BATCH        256
#define EMBED_DIM    512
#define NUM_CLASSES  100000
#define NUM_SUB      3
#define CK           (NUM_CLASSES * NUM_SUB)   // 300000 weight rows
#define BM           128                        // batch rows per CTA
#define BN           96                         // 32 classes * 3 subcenters
#define CPT          32                         // classes per tile
#define NTILES       (CK / BN)                  // 3125
#define NCTAS        (NTILES * 2)               // 6250 (2 M-halves)
#define KC           32                         // fp32 k-elems per chunk (128B rows)
#define NCH          (EMBED_DIM / KC)           // 16
#define NTHREADS     192                        // 6 warps: 2M x 3N

#define COS_M  0.87758256189037276f
#define SIN_M  0.47942553860420301f
#define TH_C   (-0.87758256189037276f)
#define MM_C   0.23971276930210150f
#define SCALE_C 64.0f

// SMEM layout (bytes)
#define SM_RNORM 0                  // 96 floats, pad to 512
#define SM_BS    512                // 4 bufs * 6144 B (96 rows * 64B fp16); reused as Cs (64x96 fl) in epilogue
#define SM_AS    25088              // 4 stages * 8192 B (128 rows * 64B fp16)
#define SMEM_TOTAL (25088 + 4*8192)    // 57856

// ============================ PTX helpers ============================
__device__ __forceinline__ uint32_t smem_u32(const void* p) {
    uint32_t a;
    asm("{ .reg .u64 t; cvta.to.shared.u64 t, %1; cvt.u32.u64 %0, t; }" : "=r"(a) : "l"(p));
    return a;
}

__device__ __forceinline__ void ldmatrix_x4(uint32_t* r, uint32_t addr) {
    asm volatile("ldmatrix.sync.aligned.m8n8.x4.shared.b16 {%0,%1,%2,%3}, [%4];"
                 : "=r"(r[0]), "=r"(r[1]), "=r"(r[2]), "=r"(r[3]) : "r"(addr));
}

__device__ __forceinline__ void mma_f16(float* c, const uint32_t* a, const uint32_t* b) {
    asm volatile("mma.sync.aligned.m16n8k16.row.col.f32.f16.f16.f32 "
                 "{%0,%1,%2,%3}, {%4,%5,%6,%7}, {%8,%9}, {%0,%1,%2,%3};"
                 : "+f"(c[0]), "+f"(c[1]), "+f"(c[2]), "+f"(c[3])
                 : "r"(a[0]), "r"(a[1]), "r"(a[2]), "r"(a[3]), "r"(b[0]), "r"(b[1]));
}

#define CP_COMMIT() asm volatile("cp.async.commit_group;" ::: "memory")
#define CP_WAIT2()  asm volatile("cp.async.wait_group 2;" ::: "memory")

// ============================ device scratch ============================
__device__ __align__(128) __half g_A16[BATCH * EMBED_DIM];   // normalized embeddings, fp16
__device__ float g_partial[BATCH * NTILES];                  // [m][tile]
__device__ float g_label[BATCH];

// ============================ kernel 1: normalize embeddings -> fp16 ============================
__global__ void normalize_kernel(const float* __restrict__ e) {
    int r = blockIdx.x, t = threadIdx.x;
    float v[4];
    float s = 0.f;
#pragma unroll
    for (int i = 0; i < 4; i++) { v[i] = e[r * EMBED_DIM + t + i * 128]; s = fmaf(v[i], v[i], s); }
#pragma unroll
    for (int off = 16; off > 0; off >>= 1) s += __shfl_xor_sync(0xFFFFFFFFu, s, off);
    __shared__ float ws[4];
    if ((t & 31) == 0) ws[t >> 5] = s;
    __syncthreads();
    float tot = ws[0] + ws[1] + ws[2] + ws[3];
    float rn = rsqrtf(fmaxf(tot, 1e-24f));
#pragma unroll
    for (int i = 0; i < 4; i++) g_A16[r * EMBED_DIM + t + i * 128] = __float2half_rn(v[i] * rn);
}

// ============================ kernel 2: fused GEMM + ArcFace epilogue ============================
__global__ __launch_bounds__(NTHREADS, 2) void gemm_kernel(
    const float* __restrict__ W, const int* __restrict__ labels)
{
    extern __shared__ char smem[];
    const uint32_t sb = smem_u32(smem);
    const int tid = threadIdx.x;
    const int wid = tid >> 5;
    const int L   = tid & 31;
    const int wm  = wid & 1;      // 0..1 (M blocks of 64)
    const int wn  = wid >> 1;     // 0..2 (N blocks of 32)
    const int tile  = blockIdx.x >> 1;
    const int mhalf = blockIdx.x & 1;

    uint64_t gA;
    asm("cvta.to.global.u64 %0, %1;" : "=l"(gA) : "l"((void*)g_A16));

    // ---- B global-load mapping: 4 rows (brow0 + 24j), one float4 each per chunk ----
    const int brow0 = tid >> 3;   // 0..23
    const int bg    = tid & 7;    // 16B group within 128B chunk-row
    const float* wpB = W + ((long)tile * BN + brow0) * EMBED_DIM + bg * 4;
#define WROWSTRIDE (24 * EMBED_DIM)

    // B STS addresses (fp16, swizzled), buf 0 base, 4 rows
    uint32_t sAddr[4];
#pragma unroll
    for (int j = 0; j < 4; j++) {
        int row = brow0 + 24 * j;
        sAddr[j] = sb + SM_BS + row * 64
                 + ((((bg >> 1)) ^ ((row >> 1) & 3)) << 4) + ((bg & 1) << 3);
    }

    // ---- issue B prologue LDGs ASAP (chunks 0,1 direct; chunk 2 to regs) ----
    float4 t0[4], t1[4], breg[4];
#pragma unroll
    for (int j = 0; j < 4; j++) t0[j] = *reinterpret_cast<const float4*>(wpB + j * WROWSTRIDE);
#pragma unroll
    for (int j = 0; j < 4; j++) t1[j] = *reinterpret_cast<const float4*>(wpB + j * WROWSTRIDE + KC);
#pragma unroll
    for (int j = 0; j < 4; j++) breg[j] = *reinterpret_cast<const float4*>(wpB + j * WROWSTRIDE + 2 * KC);

    // ---- A cp.async mapping: tid<128, 4 rows each ----
    uint32_t aDst[4];
    uint64_t aSrc[4];
    {
        const int r0 = (tid & 127) >> 2, g = tid & 3;
#pragma unroll
        for (int i = 0; i < 4; i++) {
            int r = r0 + i * 32;
            aDst[i] = sb + SM_AS + r * 64 + ((g ^ ((r >> 1) & 3)) << 4);
            aSrc[i] = gA + (uint64_t)((mhalf * BM + r) * EMBED_DIM + g * 8) * 2;
        }
    }
    auto cpasync_a = [&](int ch, uint32_t stOff) {
        if (tid < 128) {
            const uint32_t co = (uint32_t)ch * 64;
#pragma unroll
            for (int i = 0; i < 4; i++)
                asm volatile("cp.async.cg.shared.global [%0], [%1], 16;"
                             :: "r"(aDst[i] + stOff), "l"(aSrc[i] + co) : "memory");
        }
    };

    // ---- ldmatrix addresses (stage/buf 0 bases) ----
    const int sel = L >> 3, lr = L & 7;
    uint32_t aAddr[4][2], bAddr[2][2];
#pragma unroll
    for (int i = 0; i < 4; i++)
#pragma unroll
        for (int s = 0; s < 2; s++) {
            int row = wm * 64 + i * 16 + ((sel & 1) << 3) + lr;
            int kg  = 2 * s + (sel >> 1);
            aAddr[i][s] = sb + SM_AS + row * 64 + ((kg ^ ((row >> 1) & 3)) << 4);
        }
#pragma unroll
    for (int j0 = 0; j0 < 2; j0++)
#pragma unroll
        for (int s = 0; s < 2; s++) {
            int n  = wn * 32 + (2 * j0 + (sel >> 1)) * 8 + lr;
            int kg = 2 * s + (sel & 1);
            bAddr[j0][s] = sb + SM_BS + n * 64 + ((kg ^ ((n >> 1) & 3)) << 4);
        }

    float ss[4] = {0.f, 0.f, 0.f, 0.f};
    auto sts_b = [&](uint32_t addr, const float4 v, int j) {
        ss[j] += v.x * v.x + v.y * v.y + v.z * v.z + v.w * v.w;
        __half2 h0 = __floats2half2_rn(v.x, v.y);
        __half2 h1 = __floats2half2_rn(v.z, v.w);
        uint32_t u0 = *reinterpret_cast<uint32_t*>(&h0);
        uint32_t u1 = *reinterpret_cast<uint32_t*>(&h1);
        asm volatile("st.shared.v2.b32 [%0], {%1,%2};" :: "r"(addr), "r"(u0), "r"(u1) : "memory");
    };

    // ---- prime A pipeline (stages 0,1,2) + store B chunks 0,1 ----
    cpasync_a(0, 0);     CP_COMMIT();
    cpasync_a(1, 8192);  CP_COMMIT();
#pragma unroll
    for (int j = 0; j < 4; j++) sts_b(sAddr[j], t0[j], j);
#pragma unroll
    for (int j = 0; j < 4; j++) sts_b(sAddr[j] + 6144, t1[j], j);
    cpasync_a(2, 16384); CP_COMMIT();

    // ---- accumulators ----
    float c[4][4][4];
#pragma unroll
    for (int i = 0; i < 4; i++)
#pragma unroll
        for (int j = 0; j < 4; j++)
#pragma unroll
            for (int q = 0; q < 4; q++) c[i][j][q] = 0.f;

    // ---- mainloop: 16 chunks, unrolled by 4 (stage/buf period) ----
#pragma unroll 1
    for (int k4 = 0; k4 < 4; k4++) {
#pragma unroll
        for (int u = 0; u < 4; u++) {
            const int k = k4 * 4 + u;
            CP_WAIT2();                                   // A(k) complete (this thread)
            if (k <= 13) {                                // STS B chunk k+2 (loaded at k-1)
                const uint32_t bo = ((u + 2) & 3) * 6144;
#pragma unroll
                for (int j = 0; j < 4; j++) sts_b(sAddr[j] + bo, breg[j], j);
            }
            __syncthreads();                              // A(k) + B(k) visible to all
            if (k <= 12) {                                // LDG B chunk k+3 (single buffer, 1 ahead)
#pragma unroll
                for (int j = 0; j < 4; j++)
                    breg[j] = *reinterpret_cast<const float4*>(wpB + j * WROWSTRIDE + (k + 3) * KC);
                cpasync_a(k + 3, (uint32_t)((u + 3) & 3) * 8192);   // A stage k+3
            }
            CP_COMMIT();
            // ---- compute chunk k ----
            const uint32_t aOff = (uint32_t)u * 8192, bOff = (uint32_t)u * 6144;
#pragma unroll
            for (int s = 0; s < 2; s++) {
                uint32_t a[4][4];
#pragma unroll
                for (int i = 0; i < 4; i++) ldmatrix_x4(a[i], aAddr[i][s] + aOff);
                uint32_t b[4][2];
#pragma unroll
                for (int j0 = 0; j0 < 2; j0++) {
                    uint32_t r[4];
                    ldmatrix_x4(r, bAddr[j0][s] + bOff);
                    b[2 * j0][0] = r[0]; b[2 * j0][1] = r[1];
                    b[2 * j0 + 1][0] = r[2]; b[2 * j0 + 1][1] = r[3];
                }
#pragma unroll
                for (int i = 0; i < 4; i++)
#pragma unroll
                    for (int j = 0; j < 4; j++) mma_f16(c[i][j], a[i], b[j]);
            }
        }
    }

    // ---- weight-row rnorm (from conversion-time sumsq; reduce over bg lanes) ----
#pragma unroll
    for (int o = 1; o < 8; o <<= 1)
#pragma unroll
        for (int j = 0; j < 4; j++) ss[j] += __shfl_xor_sync(0xFFFFFFFFu, ss[j], o);
    __syncthreads();            // all B-buf reads done before rnorm/Cs phase
    float* rn = reinterpret_cast<float*>(smem + SM_RNORM);
    if ((L & 7) == 0) {
#pragma unroll
        for (int j = 0; j < 4; j++) rn[brow0 + 24 * j] = rsqrtf(fmaxf(ss[j], 1e-24f));
    }
    __syncthreads();

    // ---- epilogue: 2 passes of 64 rows staged into B region (XOR-swizzled, 64x96 floats) ----
    const int class0 = tile * CPT;
    float* Cs = reinterpret_cast<float*>(smem + SM_BS);
#pragma unroll 1
    for (int p = 0; p < 2; p++) {
        if (wm == p) {
#pragma unroll
            for (int i = 0; i < 4; i++) {
                int rl = i * 16 + (L >> 2);
                const int swz = (rl & 7) << 2;
#pragma unroll
                for (int j = 0; j < 4; j++) {
                    int col = wn * 32 + j * 8 + 2 * (L & 3);
                    float s0 = rn[col], s1 = rn[col + 1];
                    Cs[rl * 96       + (col ^ swz)]       = c[i][j][0] * s0;
                    Cs[rl * 96       + ((col + 1) ^ swz)] = c[i][j][1] * s1;
                    Cs[(rl + 8) * 96 + (col ^ swz)]       = c[i][j][2] * s0;
                    Cs[(rl + 8) * 96 + ((col + 1) ^ swz)] = c[i][j][3] * s1;
                }
            }
        }
        __syncthreads();
        if (tid < 64) {
            const int m = mhalf * BM + p * 64 + tid;
            const int labloc = labels[m] - class0;     // in [0,32) iff label in this tile
            const float* row = Cs + tid * 96;
            const int swz = (tid & 7) << 2;
            float sum = 0.f;
#pragma unroll 4
            for (int cc = 0; cc < CPT; cc++) {
                float v0 = row[(3 * cc) ^ swz];
                float v1 = row[(3 * cc + 1) ^ swz];
                float v2 = row[(3 * cc + 2) ^ swz];
                float cosv = fmaxf(v0, fmaxf(v1, v2));
                float val = cosv;
                if (cc == labloc) {
                    float sine = sqrtf(fmaxf(1.f - cosv * cosv, 0.f));
                    float phi = cosv * COS_M - sine * SIN_M;
                    phi = (cosv > TH_C) ? phi : (cosv - MM_C);
                    val = phi;
                    g_label[m] = SCALE_C * phi;
                }
                sum += __expf(SCALE_C * (val - 1.f));
            }
            g_partial[(long)m * NTILES + tile] = sum;
        }
        __syncthreads();
    }
}

// ============================ kernel 3: finalize (atomic mean) ============================
__global__ void finalize_kernel(float* __restrict__ out) {
    const int m = blockIdx.x;
    const int t = threadIdx.x;   // 256 threads
    const float* row = g_partial + (long)m * NTILES;
    float s = 0.f;
    for (int i = t; i < NTILES; i += 256) s += row[i];
#pragma unroll
    for (int off = 16; off > 0; off >>= 1) s += __shfl_xor_sync(0xFFFFFFFFu, s, off);
    __shared__ float ws[8];
    if ((t & 31) == 0) ws[t >> 5] = s;
    __syncthreads();
    if (t == 0) {
        float tot = 0.f;
#pragma unroll
        for (int i = 0; i < 8; i++) tot += ws[i];
        float loss = SCALE_C + logf(tot) - g_label[m];
        atomicAdd(out, loss * (1.0f / 256.0f));
    }
}

// ============================ host launch ============================
extern "C" void kernel_launch(void* const* d_in, const int* in_sizes, int n_in,
                              void* d_out, int out_size) {
    const float* emb    = (const float*)d_in[0];
    const int*   labels = (const int*)d_in[1];    // JAX w/o x64: int64 randint -> int32
    const float* weight = (const float*)d_in[2];
    float* out = (float*)d_out;

    cudaFuncSetAttribute(gemm_kernel, cudaFuncAttributeMaxDynamicSharedMemorySize, SMEM_TOTAL);

    cudaMemsetAsync(d_out, 0, sizeof(float));
    normalize_kernel<<<BATCH, 128>>>(emb);
    gemm_kernel<<<NCTAS, NTHREADS, SMEM_TOTAL>>>(weight, labels);
    finalize_kernel<<<BATCH, 256>>>(out);
}

// round 7
// speedup vs baseline: 1.3894x; 1.3894x over previous
#include <cuda_runtime.h>
#include <cuda_fp16.h>
#include <cstdint>

// ============================ problem constants ============================
#define BATCH        256
#define EMBED_DIM    512
#define NUM_CLASSES  100000
#define NUM_SUB      3
#define CK           (NUM_CLASSES * NUM_SUB)   // 300000 weight rows
#define BN           96                         // 32 classes * 3 subcenters
#define CPT          32                         // classes per tile
#define NTILES       (CK / BN)                  // 3125
#define KC           32                         // fp32 k-elems per chunk (128B rows)
#define NCH          (EMBED_DIM / KC)           // 16
#define NTHREADS     384                        // 12 warps: 4M x 3N

#define COS_M  0.87758256189037276f
#define SIN_M  0.47942553860420301f
#define TH_C   (-0.87758256189037276f)
#define MM_C   0.23971276930210150f
#define SCALE_C 64.0f

// SMEM layout (bytes)
#define SM_RNORM 0                  // 96 floats (384 B), pad to 512
#define SM_BS    512                // 4 bufs * 6144 B (96 rows * 64B fp16)
#define SM_AS    25088              // 4 stages * 16384 B (256 rows * 64B fp16)
#define SM_CS    25088              // reuses A region post-mainloop: 128*97*4 = 49664
#define SMEM_TOTAL (25088 + 4*16384)   // 90624

// ============================ PTX helpers ============================
__device__ __forceinline__ uint32_t smem_u32(const void* p) {
    uint32_t a;
    asm("{ .reg .u64 t; cvta.to.shared.u64 t, %1; cvt.u32.u64 %0, t; }" : "=r"(a) : "l"(p));
    return a;
}

__device__ __forceinline__ void ldmatrix_x4(uint32_t* r, uint32_t addr) {
    asm volatile("ldmatrix.sync.aligned.m8n8.x4.shared.b16 {%0,%1,%2,%3}, [%4];"
                 : "=r"(r[0]), "=r"(r[1]), "=r"(r[2]), "=r"(r[3]) : "r"(addr));
}

__device__ __forceinline__ void mma_f16(float* c, const uint32_t* a, const uint32_t* b) {
    asm volatile("mma.sync.aligned.m16n8k16.row.col.f32.f16.f16.f32 "
                 "{%0,%1,%2,%3}, {%4,%5,%6,%7}, {%8,%9}, {%0,%1,%2,%3};"
                 : "+f"(c[0]), "+f"(c[1]), "+f"(c[2]), "+f"(c[3])
                 : "r"(a[0]), "r"(a[1]), "r"(a[2]), "r"(a[3]), "r"(b[0]), "r"(b[1]));
}

#define CP_COMMIT() asm volatile("cp.async.commit_group;" ::: "memory")
#define CP_WAIT2()  asm volatile("cp.async.wait_group 2;" ::: "memory")

// ============================ device scratch ============================
__device__ __align__(128) __half g_A16[BATCH * EMBED_DIM];   // normalized embeddings, fp16
__device__ float g_partial[BATCH * NTILES];                  // [m][tile]
__device__ float g_label[BATCH];
__device__ float g_loss[BATCH];

// ============================ kernel 1: normalize embeddings -> fp16 ============================
__global__ void normalize_kernel(const float* __restrict__ e) {
    int r = blockIdx.x, t = threadIdx.x;
    float v[4];
    float s = 0.f;
#pragma unroll
    for (int i = 0; i < 4; i++) { v[i] = e[r * EMBED_DIM + t + i * 128]; s = fmaf(v[i], v[i], s); }
#pragma unroll
    for (int off = 16; off > 0; off >>= 1) s += __shfl_xor_sync(0xFFFFFFFFu, s, off);
    __shared__ float ws[4];
    if ((t & 31) == 0) ws[t >> 5] = s;
    __syncthreads();
    float tot = ws[0] + ws[1] + ws[2] + ws[3];
    float rn = rsqrtf(fmaxf(tot, 1e-24f));
#pragma unroll
    for (int i = 0; i < 4; i++) g_A16[r * EMBED_DIM + t + i * 128] = __float2half_rn(v[i] * rn);
}

// ============================ kernel 2: fused GEMM + ArcFace epilogue ============================
__global__ __launch_bounds__(NTHREADS) void gemm_kernel(
    const float* __restrict__ W, const int* __restrict__ labels)
{
    extern __shared__ char smem[];
    const uint32_t sb = smem_u32(smem);
    const int tid = threadIdx.x;
    const int wid = tid >> 5;
    const int L   = tid & 31;
    const int wm  = wid & 3;      // 0..3 (M blocks of 64)
    const int wn  = wid >> 2;     // 0..2 (N blocks of 32)
    const int tile = blockIdx.x;

    uint64_t gA;
    asm("cvta.to.global.u64 %0, %1;" : "=l"(gA) : "l"((void*)g_A16));

    // ---- B global-load mapping: 2 float4 per thread per chunk ----
    const int brow0 = tid >> 3;   // 0..47
    const int bg    = tid & 7;    // 16B group within 128B chunk-row
    const float* wp0 = W + ((long)tile * BN + brow0) * EMBED_DIM + bg * 4;
    const float* wp1 = W + ((long)tile * BN + brow0 + 48) * EMBED_DIM + bg * 4;

    // ---- precomputed smem addresses (registers) ----
    const uint32_t stsSw  = ((((bg >> 1)) ^ ((brow0 >> 1) & 3)) << 4) + ((bg & 1) << 3);
    const uint32_t stsSw1 = ((((bg >> 1)) ^ (((brow0 + 48) >> 1) & 3)) << 4) + ((bg & 1) << 3);
    const uint32_t sAddr0 = sb + SM_BS + brow0 * 64 + stsSw;
    const uint32_t sAddr1 = sb + SM_BS + (brow0 + 48) * 64 + stsSw1;

    uint32_t aDst[4];
    uint64_t aSrc[4];
    {
        const int r0 = (tid & 255) >> 2, g = tid & 3;
#pragma unroll
        for (int i = 0; i < 4; i++) {
            int r = r0 + i * 64;
            aDst[i] = sb + SM_AS + r * 64 + ((g ^ ((r >> 1) & 3)) << 4);
            aSrc[i] = gA + (uint64_t)(r * EMBED_DIM + g * 8) * 2;
        }
    }

    const int sel = L >> 3, lr = L & 7;
    uint32_t aAddr[4][2], bAddr[2][2];
#pragma unroll
    for (int i = 0; i < 4; i++)
#pragma unroll
        for (int s = 0; s < 2; s++) {
            int row = wm * 64 + i * 16 + ((sel & 1) << 3) + lr;
            int kg  = 2 * s + (sel >> 1);
            aAddr[i][s] = sb + SM_AS + row * 64 + ((kg ^ ((row >> 1) & 3)) << 4);
        }
#pragma unroll
    for (int j0 = 0; j0 < 2; j0++)
#pragma unroll
        for (int s = 0; s < 2; s++) {
            int n  = wn * 32 + (2 * j0 + (sel >> 1)) * 8 + lr;
            int kg = 2 * s + (sel & 1);
            bAddr[j0][s] = sb + SM_BS + n * 64 + ((kg ^ ((n >> 1) & 3)) << 4);
        }

    float4 breg0[2], breg1[2];
    float ss0 = 0.f, ss1 = 0.f;

    auto sts_b = [&](uint32_t addr, const float4 v, float& ss) {
        ss += v.x * v.x + v.y * v.y + v.z * v.z + v.w * v.w;
        __half2 h0 = __floats2half2_rn(v.x, v.y);
        __half2 h1 = __floats2half2_rn(v.z, v.w);
        uint32_t u0 = *reinterpret_cast<uint32_t*>(&h0);
        uint32_t u1 = *reinterpret_cast<uint32_t*>(&h1);
        asm volatile("st.shared.v2.b32 [%0], {%1,%2};" :: "r"(addr), "r"(u0), "r"(u1) : "memory");
    };
    auto cpasync_a = [&](int ch, uint32_t stOff) {
        if (tid < 256) {
            const uint32_t co = (uint32_t)ch * 64;
#pragma unroll
            for (int i = 0; i < 4; i++)
                asm volatile("cp.async.cg.shared.global [%0], [%1], 16;"
                             :: "r"(aDst[i] + stOff), "l"(aSrc[i] + co) : "memory");
        }
    };

    // ---- accumulators ----
    float c[4][4][4];
#pragma unroll
    for (int i = 0; i < 4; i++)
#pragma unroll
        for (int j = 0; j < 4; j++)
#pragma unroll
            for (int q = 0; q < 4; q++) c[i][j][q] = 0.f;

    // ---- prologue: B chunks 0,1 -> bufs 0,1; LDG chunks 2,3; A stages 0,1,2 ----
    {
        float4 t0 = *reinterpret_cast<const float4*>(wp0);
        float4 t1 = *reinterpret_cast<const float4*>(wp1);
        float4 t2 = *reinterpret_cast<const float4*>(wp0 + KC);
        float4 t3 = *reinterpret_cast<const float4*>(wp1 + KC);
        sts_b(sAddr0, t0, ss0);
        sts_b(sAddr1, t1, ss1);
        sts_b(sAddr0 + 6144, t2, ss0);
        sts_b(sAddr1 + 6144, t3, ss1);
        breg0[0] = *reinterpret_cast<const float4*>(wp0 + 2 * KC);
        breg1[0] = *reinterpret_cast<const float4*>(wp1 + 2 * KC);
        breg0[1] = *reinterpret_cast<const float4*>(wp0 + 3 * KC);
        breg1[1] = *reinterpret_cast<const float4*>(wp1 + 3 * KC);
        cpasync_a(0, 0);     CP_COMMIT();
        cpasync_a(1, 16384); CP_COMMIT();
        cpasync_a(2, 32768); CP_COMMIT();
    }

    // ---- mainloop: 16 chunks, unrolled by 4 (stage/buf period) ----
#pragma unroll 1
    for (int k4 = 0; k4 < 4; k4++) {
#pragma unroll
        for (int u = 0; u < 4; u++) {
            const int k = k4 * 4 + u;
            CP_WAIT2();                                   // A(k) complete (this thread)
            if (k <= 13) {                                // STS B chunk k+2 (2 ahead of use)
                const uint32_t bo = ((u + 2) & 3) * 6144;
                sts_b(sAddr0 + bo, breg0[u & 1], ss0);
                sts_b(sAddr1 + bo, breg1[u & 1], ss1);
            }
            __syncthreads();                              // all A(k) copies + B(k) visible
            if (k <= 11) {                                // LDG B chunk k+4
                breg0[u & 1] = *reinterpret_cast<const float4*>(wp0 + (k + 4) * KC);
                breg1[u & 1] = *reinterpret_cast<const float4*>(wp1 + (k + 4) * KC);
            }
            if (k <= 12) cpasync_a(k + 3, ((u + 3) & 3) * 16384);   // A stage k+3
            CP_COMMIT();
            // ---- compute chunk k ----
            const uint32_t aOff = (uint32_t)u * 16384, bOff = (uint32_t)u * 6144;
#pragma unroll
            for (int s = 0; s < 2; s++) {
                uint32_t a[4][4];
#pragma unroll
                for (int i = 0; i < 4; i++) ldmatrix_x4(a[i], aAddr[i][s] + aOff);
                uint32_t b[4][2];
#pragma unroll
                for (int j0 = 0; j0 < 2; j0++) {
                    uint32_t r[4];
                    ldmatrix_x4(r, bAddr[j0][s] + bOff);
                    b[2 * j0][0] = r[0]; b[2 * j0][1] = r[1];
                    b[2 * j0 + 1][0] = r[2]; b[2 * j0 + 1][1] = r[3];
                }
#pragma unroll
                for (int i = 0; i < 4; i++)
#pragma unroll
                    for (int j = 0; j < 4; j++) mma_f16(c[i][j], a[i], b[j]);
            }
        }
    }

    // ---- weight-row rnorm (from conversion-time sumsq) ----
#pragma unroll
    for (int o = 1; o < 8; o <<= 1) {
        ss0 += __shfl_xor_sync(0xFFFFFFFFu, ss0, o);
        ss1 += __shfl_xor_sync(0xFFFFFFFFu, ss1, o);
    }
    float* rn = reinterpret_cast<float*>(smem + SM_RNORM);
    if ((L & 7) == 0) {
        rn[brow0]      = rsqrtf(fmaxf(ss0, 1e-24f));
        rn[brow0 + 48] = rsqrtf(fmaxf(ss1, 1e-24f));
    }
    __syncthreads();

    // ---- epilogue: two half-M passes through smem staging ----
    const int class0 = tile * CPT;
    float* Cs = reinterpret_cast<float*>(smem + SM_CS);
#pragma unroll 1
    for (int p = 0; p < 2; p++) {
        if ((wm >> 1) == p) {
            const int mr0 = (wm & 1) * 64;
#pragma unroll
            for (int i = 0; i < 4; i++) {
                int r = mr0 + i * 16 + (L >> 2);
#pragma unroll
                for (int j = 0; j < 4; j++) {
                    int col = wn * 32 + j * 8 + 2 * (L & 3);
                    float s0 = rn[col], s1 = rn[col + 1];
                    Cs[r * 97 + col]           = c[i][j][0] * s0;
                    Cs[r * 97 + col + 1]       = c[i][j][1] * s1;
                    Cs[(r + 8) * 97 + col]     = c[i][j][2] * s0;
                    Cs[(r + 8) * 97 + col + 1] = c[i][j][3] * s1;
                }
            }
        }
        __syncthreads();
        if (tid < 128) {
            const int m = p * 128 + tid;
            const int labloc = labels[m] - class0;     // in [0,32) iff label in this tile
            const float* row = Cs + tid * 97;
            float sum = 0.f;
#pragma unroll 4
            for (int cc = 0; cc < CPT; cc++) {
                float v0 = row[3 * cc], v1 = row[3 * cc + 1], v2 = row[3 * cc + 2];
                float cosv = fmaxf(v0, fmaxf(v1, v2));
                float val = cosv;
                if (cc == labloc) {
                    float sine = sqrtf(fmaxf(1.f - cosv * cosv, 0.f));
                    float phi = cosv * COS_M - sine * SIN_M;
                    phi = (cosv > TH_C) ? phi : (cosv - MM_C);
                    val = phi;
                    g_label[m] = SCALE_C * phi;
                }
                sum += __expf(SCALE_C * (val - 1.f));
            }
            g_partial[m * NTILES + tile] = sum;
        }
        __syncthreads();
    }
}

// ============================ kernel 3a: per-row reduce over tiles ============================
__global__ void finalize1_kernel() {
    const int m = blockIdx.x;
    const int t = threadIdx.x;   // 256 threads
    const float* row = g_partial + (long)m * NTILES;
    float s = 0.f;
    for (int i = t; i < NTILES; i += 256) s += row[i];
#pragma unroll
    for (int off = 16; off > 0; off >>= 1) s += __shfl_xor_sync(0xFFFFFFFFu, s, off);
    __shared__ float ws[8];
    if ((t & 31) == 0) ws[t >> 5] = s;
    __syncthreads();
    if (t == 0) {
        float tot = 0.f;
#pragma unroll
        for (int i = 0; i < 8; i++) tot += ws[i];
        g_loss[m] = SCALE_C + logf(tot) - g_label[m];
    }
}

// ============================ kernel 3b: mean over batch ============================
__global__ void finalize2_kernel(float* __restrict__ out) {
    const int m = threadIdx.x;   // 256 threads
    float v = g_loss[m];
#pragma unroll
    for (int off = 16; off > 0; off >>= 1) v += __shfl_xor_sync(0xFFFFFFFFu, v, off);
    __shared__ float ws[8];
    if ((m & 31) == 0) ws[m >> 5] = v;
    __syncthreads();
    if (m == 0) {
        float tot = 0.f;
#pragma unroll
        for (int i = 0; i < 8; i++) tot += ws[i];
        out[0] = tot * (1.0f / 256.0f);
    }
}

// ============================ host launch ============================
extern "C" void kernel_launch(void* const* d_in, const int* in_sizes, int n_in,
                              void* d_out, int out_size) {
    const float* emb    = (const float*)d_in[0];
    const int*   labels = (const int*)d_in[1];    // JAX w/o x64: int64 randint -> int32
    const float* weight = (const float*)d_in[2];
    float* out = (float*)d_out;

    cudaFuncSetAttribute(gemm_kernel, cudaFuncAttributeMaxDynamicSharedMemorySize, SMEM_TOTAL);

    // Launch order puts gemm at stream indices 1, 5, 9, ... so ncu (-s 5 -c 1)
    // captures the gemm on the second replay instead of a trivial kernel.
    normalize_kernel<<<BATCH, 128>>>(emb);
    gemm_kernel<<<NTILES, NTHREADS, SMEM_TOTAL>>>(weight, labels);
    finalize1_kernel<<<BATCH, 256>>>();
    finalize2_kernel<<<1, 256>>>(out);
}

// round 9
// speedup vs baseline: 1.5991x; 1.1509x over previous
#include <cuda_runtime.h>
#include <cuda_fp16.h>
#include <cstdint>

// ============================ problem constants ============================
#define BATCH        256
#define EMBED_DIM    512
#define NUM_CLASSES  100000
#define NUM_SUB      3
#define CK           (NUM_CLASSES * NUM_SUB)   // 300000 weight rows
#define BN           96                         // 32 classes * 3 subcenters
#define CPT          32                         // classes per tile
#define NTILES       (CK / BN)                  // 3125
#define KC           32                         // fp32 k-elems per chunk (128B rows)
#define NCH          (EMBED_DIM / KC)           // 16
#define NTHREADS     384                        // 12 warps: 4M x 3N

#define COS_M  0.87758256189037276f
#define SIN_M  0.47942553860420301f
#define TH_C   (-0.87758256189037276f)
#define MM_C   0.23971276930210150f
#define SCALE_C 64.0f

// SMEM layout (bytes)
#define SM_RNORM 0                   // 96 floats, pad to 512
#define SM_BS    512                 // 4 bufs * 6144 B (96 rows * 64B fp16)
#define SM_AS    25088               // 8 stages * 16384 B (256 rows * 64B fp16)
#define SM_CS    25088               // reuses A region post-mainloop: 128*97*4 = 49664
#define SM_PART  (25088 + 50176)     // 128 floats partial scratch
#define SMEM_TOTAL (25088 + 8*16384) // 156160

// ============================ PTX helpers ============================
__device__ __forceinline__ uint32_t smem_u32(const void* p) {
    uint32_t a;
    asm("{ .reg .u64 t; cvta.to.shared.u64 t, %1; cvt.u32.u64 %0, t; }" : "=r"(a) : "l"(p));
    return a;
}

__device__ __forceinline__ void ldmatrix_x4(uint32_t* r, uint32_t addr) {
    asm volatile("ldmatrix.sync.aligned.m8n8.x4.shared.b16 {%0,%1,%2,%3}, [%4];"
                 : "=r"(r[0]), "=r"(r[1]), "=r"(r[2]), "=r"(r[3]) : "r"(addr));
}

__device__ __forceinline__ void mma_f16(float* c, const uint32_t* a, const uint32_t* b) {
    asm volatile("mma.sync.aligned.m16n8k16.row.col.f32.f16.f16.f32 "
                 "{%0,%1,%2,%3}, {%4,%5,%6,%7}, {%8,%9}, {%0,%1,%2,%3};"
                 : "+f"(c[0]), "+f"(c[1]), "+f"(c[2]), "+f"(c[3])
                 : "r"(a[0]), "r"(a[1]), "r"(a[2]), "r"(a[3]), "r"(b[0]), "r"(b[1]));
}

#define CP_COMMIT() asm volatile("cp.async.commit_group;" ::: "memory")
#define CP_WAIT1()  asm volatile("cp.async.wait_group 1;" ::: "memory")

// ============================ device scratch ============================
__device__ __align__(128) __half g_A16[BATCH * EMBED_DIM];   // normalized embeddings, fp16
__device__ float g_partial[BATCH * NTILES];                  // [m][tile]
__device__ float g_label[BATCH];
__device__ float g_loss[BATCH];

// ============================ kernel 1: normalize embeddings -> fp16 ============================
__global__ void normalize_kernel(const float* __restrict__ e) {
    int r = blockIdx.x, t = threadIdx.x;
    float v[4];
    float s = 0.f;
#pragma unroll
    for (int i = 0; i < 4; i++) { v[i] = e[r * EMBED_DIM + t + i * 128]; s = fmaf(v[i], v[i], s); }
#pragma unroll
    for (int off = 16; off > 0; off >>= 1) s += __shfl_xor_sync(0xFFFFFFFFu, s, off);
    __shared__ float ws[4];
    if ((t & 31) == 0) ws[t >> 5] = s;
    __syncthreads();
    float tot = ws[0] + ws[1] + ws[2] + ws[3];
    float rn = rsqrtf(fmaxf(tot, 1e-24f));
#pragma unroll
    for (int i = 0; i < 4; i++) g_A16[r * EMBED_DIM + t + i * 128] = __float2half_rn(v[i] * rn);
}

// ============================ kernel 2: fused GEMM + ArcFace epilogue ============================
__global__ __launch_bounds__(NTHREADS) void gemm_kernel(
    const float* __restrict__ W, const int* __restrict__ labels)
{
    extern __shared__ char smem[];
    const uint32_t sb = smem_u32(smem);
    const int tid = threadIdx.x;
    const int wid = tid >> 5;
    const int L   = tid & 31;
    const int wm  = wid & 3;      // 0..3 (M blocks of 64)
    const int wn  = wid >> 2;     // 0..2 (N blocks of 32)
    const int tile = blockIdx.x;

    uint64_t gA;
    asm("cvta.to.global.u64 %0, %1;" : "=l"(gA) : "l"((void*)g_A16));

    // ---- B global-load mapping: 2 float4 per thread per chunk ----
    const int brow0 = tid >> 3;   // 0..47
    const int bg    = tid & 7;    // 16B group within 128B chunk-row
    const float* wp0 = W + ((long)tile * BN + brow0) * EMBED_DIM + bg * 4;
    const float* wp1 = W + ((long)tile * BN + brow0 + 48) * EMBED_DIM + bg * 4;

    // ---- precomputed smem addresses (registers) ----
    const uint32_t stsSw  = ((((bg >> 1)) ^ ((brow0 >> 1) & 3)) << 4) + ((bg & 1) << 3);
    const uint32_t stsSw1 = ((((bg >> 1)) ^ (((brow0 + 48) >> 1) & 3)) << 4) + ((bg & 1) << 3);
    const uint32_t sAddr0 = sb + SM_BS + brow0 * 64 + stsSw;
    const uint32_t sAddr1 = sb + SM_BS + (brow0 + 48) * 64 + stsSw1;

    uint32_t aDst[4];
    uint64_t aSrc[4];
    {
        const int r0 = (tid & 255) >> 2, g = tid & 3;
#pragma unroll
        for (int i = 0; i < 4; i++) {
            int r = r0 + i * 64;
            aDst[i] = sb + SM_AS + r * 64 + ((g ^ ((r >> 1) & 3)) << 4);
            aSrc[i] = gA + (uint64_t)(r * EMBED_DIM + g * 8) * 2;
        }
    }

    const int sel = L >> 3, lr = L & 7;
    uint32_t aAddr[4][2], bAddr[2][2];
#pragma unroll
    for (int i = 0; i < 4; i++)
#pragma unroll
        for (int s = 0; s < 2; s++) {
            int row = wm * 64 + i * 16 + ((sel & 1) << 3) + lr;
            int kg  = 2 * s + (sel >> 1);
            aAddr[i][s] = sb + SM_AS + row * 64 + ((kg ^ ((row >> 1) & 3)) << 4);
        }
#pragma unroll
    for (int j0 = 0; j0 < 2; j0++)
#pragma unroll
        for (int s = 0; s < 2; s++) {
            int n  = wn * 32 + (2 * j0 + (sel >> 1)) * 8 + lr;
            int kg = 2 * s + (sel & 1);
            bAddr[j0][s] = sb + SM_BS + n * 64 + ((kg ^ ((n >> 1) & 3)) << 4);
        }

    float4 breg0[2], breg1[2];
    float ss0 = 0.f, ss1 = 0.f;

    auto sts_b = [&](uint32_t addr, const float4 v, float& ss) {
        ss += v.x * v.x + v.y * v.y + v.z * v.z + v.w * v.w;
        __half2 h0 = __floats2half2_rn(v.x, v.y);
        __half2 h1 = __floats2half2_rn(v.z, v.w);
        uint32_t u0 = *reinterpret_cast<uint32_t*>(&h0);
        uint32_t u1 = *reinterpret_cast<uint32_t*>(&h1);
        asm volatile("st.shared.v2.b32 [%0], {%1,%2};" :: "r"(addr), "r"(u0), "r"(u1) : "memory");
    };
    auto cpasync_a = [&](int ch, uint32_t stOff) {
        if (tid < 256) {
            const uint32_t co = (uint32_t)ch * 64;
#pragma unroll
            for (int i = 0; i < 4; i++)
                asm volatile("cp.async.cg.shared.global [%0], [%1], 16;"
                             :: "r"(aDst[i] + stOff), "l"(aSrc[i] + co) : "memory");
        }
    };

    // ---- accumulators ----
    float c[4][4][4];
#pragma unroll
    for (int i = 0; i < 4; i++)
#pragma unroll
        for (int j = 0; j < 4; j++)
#pragma unroll
            for (int q = 0; q < 4; q++) c[i][j][q] = 0.f;

    // ---- prologue: B chunks 0,1 -> bufs 0,1; LDG chunks 2,3; A pairs (0,1) + (2,3) ----
    {
        float4 t0 = *reinterpret_cast<const float4*>(wp0);
        float4 t1 = *reinterpret_cast<const float4*>(wp1);
        float4 t2 = *reinterpret_cast<const float4*>(wp0 + KC);
        float4 t3 = *reinterpret_cast<const float4*>(wp1 + KC);
        sts_b(sAddr0, t0, ss0);
        sts_b(sAddr1, t1, ss1);
        sts_b(sAddr0 + 6144, t2, ss0);
        sts_b(sAddr1 + 6144, t3, ss1);
        breg0[0] = *reinterpret_cast<const float4*>(wp0 + 2 * KC);
        breg1[0] = *reinterpret_cast<const float4*>(wp1 + 2 * KC);
        breg0[1] = *reinterpret_cast<const float4*>(wp0 + 3 * KC);
        breg1[1] = *reinterpret_cast<const float4*>(wp1 + 3 * KC);
        cpasync_a(0, 0);
        cpasync_a(1, 16384);
        CP_COMMIT();                 // group = pair (0,1)
        cpasync_a(2, 32768);
        cpasync_a(3, 49152);
        CP_COMMIT();                 // group = pair (2,3)
    }

    // ---- mainloop: 8 chunk-pairs; one wait + one barrier per pair ----
#pragma unroll 1
    for (int t = 0; t < 2; t++) {
#pragma unroll
        for (int jp = 0; jp < 4; jp++) {
            const int p  = t * 4 + jp;    // pair index 0..7
            const int k0 = 2 * p;         // chunks k0, k0+1
            CP_WAIT1();                   // pair p's A complete (this thread)
            __syncthreads();              // A(pair p) + B(chunks k0,k0+1) visible to all
            // STS B chunks k0+2, k0+3 (consumed only after the NEXT pair's barrier)
            if (p <= 6) {
                sts_b(sAddr0 + (uint32_t)((k0 + 2) & 3) * 6144, breg0[0], ss0);
                sts_b(sAddr1 + (uint32_t)((k0 + 2) & 3) * 6144, breg1[0], ss1);
                sts_b(sAddr0 + (uint32_t)((k0 + 3) & 3) * 6144, breg0[1], ss0);
                sts_b(sAddr1 + (uint32_t)((k0 + 3) & 3) * 6144, breg1[1], ss1);
            }
            if (p <= 5) {
                // LDG B chunks k0+4, k0+5
                breg0[0] = *reinterpret_cast<const float4*>(wp0 + (k0 + 4) * KC);
                breg1[0] = *reinterpret_cast<const float4*>(wp1 + (k0 + 4) * KC);
                breg0[1] = *reinterpret_cast<const float4*>(wp0 + (k0 + 5) * KC);
                breg1[1] = *reinterpret_cast<const float4*>(wp1 + (k0 + 5) * KC);
                // A pair (k0+4, k0+5) into stages (k0+4)&7, (k0+5)&7
                cpasync_a(k0 + 4, (uint32_t)((k0 + 4) & 7) * 16384);
                cpasync_a(k0 + 5, (uint32_t)((k0 + 5) & 7) * 16384);
            }
            CP_COMMIT();
            // ---- compute chunks k0, k0+1 ----
#pragma unroll
            for (int cc = 0; cc < 2; cc++) {
                const uint32_t aOff = (uint32_t)((k0 + cc) & 7) * 16384;
                const uint32_t bOff = (uint32_t)((k0 + cc) & 3) * 6144;
#pragma unroll
                for (int s = 0; s < 2; s++) {
                    uint32_t a[4][4];
#pragma unroll
                    for (int i = 0; i < 4; i++) ldmatrix_x4(a[i], aAddr[i][s] + aOff);
                    uint32_t b[4][2];
#pragma unroll
                    for (int j0 = 0; j0 < 2; j0++) {
                        uint32_t r[4];
                        ldmatrix_x4(r, bAddr[j0][s] + bOff);
                        b[2 * j0][0] = r[0]; b[2 * j0][1] = r[1];
                        b[2 * j0 + 1][0] = r[2]; b[2 * j0 + 1][1] = r[3];
                    }
#pragma unroll
                    for (int i = 0; i < 4; i++)
#pragma unroll
                        for (int j = 0; j < 4; j++) mma_f16(c[i][j], a[i], b[j]);
                }
            }
        }
    }

    // ---- weight-row rnorm (from conversion-time sumsq) ----
#pragma unroll
    for (int o = 1; o < 8; o <<= 1) {
        ss0 += __shfl_xor_sync(0xFFFFFFFFu, ss0, o);
        ss1 += __shfl_xor_sync(0xFFFFFFFFu, ss1, o);
    }
    float* rn = reinterpret_cast<float*>(smem + SM_RNORM);
    if ((L & 7) == 0) {
        rn[brow0]      = rsqrtf(fmaxf(ss0, 1e-24f));
        rn[brow0 + 48] = rsqrtf(fmaxf(ss1, 1e-24f));
    }
    __syncthreads();

    // ---- epilogue: two half-M passes; 256 threads, 2 parts x 16 classes per row ----
    // All __syncthreads below are UNIFORM (executed by all 384 threads).
    const int class0 = tile * CPT;
    float* Cs = reinterpret_cast<float*>(smem + SM_CS);
    float* PartS = reinterpret_cast<float*>(smem + SM_PART);
#pragma unroll 1
    for (int p = 0; p < 2; p++) {
        if ((wm >> 1) == p) {
            const int mr0 = (wm & 1) * 64;
#pragma unroll
            for (int i = 0; i < 4; i++) {
                int r = mr0 + i * 16 + (L >> 2);
#pragma unroll
                for (int j = 0; j < 4; j++) {
                    int col = wn * 32 + j * 8 + 2 * (L & 3);
                    float s0 = rn[col], s1 = rn[col + 1];
                    Cs[r * 97 + col]           = c[i][j][0] * s0;
                    Cs[r * 97 + col + 1]       = c[i][j][1] * s1;
                    Cs[(r + 8) * 97 + col]     = c[i][j][2] * s0;
                    Cs[(r + 8) * 97 + col + 1] = c[i][j][3] * s1;
                }
            }
        }
        __syncthreads();                       // Cs staged

        float sum = 0.f;
        int m = 0, part = 0, row = 0;
        if (tid < 256) {
            row  = tid >> 1;                   // 0..127
            part = tid & 1;                    // classes [16*part, 16*part+16)
            m = p * 128 + row;
            const int labloc = labels[m] - class0;   // in [0,32) iff label here
            const float* rowp = Cs + row * 97;
            const int cbeg = part * 16;
#pragma unroll 4
            for (int cc = cbeg; cc < cbeg + 16; cc++) {
                float v0 = rowp[3 * cc], v1 = rowp[3 * cc + 1], v2 = rowp[3 * cc + 2];
                float cosv = fmaxf(v0, fmaxf(v1, v2));
                float val = cosv;
                if (cc == labloc) {
                    float sine = sqrtf(fmaxf(1.f - cosv * cosv, 0.f));
                    float phi = cosv * COS_M - sine * SIN_M;
                    phi = (cosv > TH_C) ? phi : (cosv - MM_C);
                    val = phi;
                    g_label[m] = SCALE_C * phi;
                }
                sum += __expf(SCALE_C * (val - 1.f));
            }
            if (part) PartS[row] = sum;
        }
        __syncthreads();                       // PartS visible
        if (tid < 256 && !part)
            g_partial[m * NTILES + tile] = sum + PartS[row];
        __syncthreads();                       // Cs/PartS free for next pass
    }
}

// ============================ kernel 3a: per-row reduce over tiles ============================
__global__ void finalize1_kernel() {
    const int m = blockIdx.x;
    const int t = threadIdx.x;   // 256 threads
    const float* row = g_partial + (long)m * NTILES;
    float s = 0.f;
    for (int i = t; i < NTILES; i += 256) s += row[i];
#pragma unroll
    for (int off = 16; off > 0; off >>= 1) s += __shfl_xor_sync(0xFFFFFFFFu, s, off);
    __shared__ float ws[8];
    if ((t & 31) == 0) ws[t >> 5] = s;
    __syncthreads();
    if (t == 0) {
        float tot = 0.f;
#pragma unroll
        for (int i = 0; i < 8; i++) tot += ws[i];
        g_loss[m] = SCALE_C + logf(tot) - g_label[m];
    }
}

// ============================ kernel 3b: mean over batch ============================
__global__ void finalize2_kernel(float* __restrict__ out) {
    const int m = threadIdx.x;   // 256 threads
    float v = g_loss[m];
#pragma unroll
    for (int off = 16; off > 0; off >>= 1) v += __shfl_xor_sync(0xFFFFFFFFu, v, off);
    __shared__ float ws[8];
    if ((m & 31) == 0) ws[m >> 5] = v;
    __syncthreads();
    if (m == 0) {
        float tot = 0.f;
#pragma unroll
        for (int i = 0; i < 8; i++) tot += ws[i];
        out[0] = tot * (1.0f / 256.0f);
    }
}

// ============================ host launch ============================
extern "C" void kernel_launch(void* const* d_in, const int* in_sizes, int n_in,
                              void* d_out, int out_size) {
    const float* emb    = (const float*)d_in[0];
    const int*   labels = (const int*)d_in[1];    // JAX w/o x64: int64 randint -> int32
    const float* weight = (const float*)d_in[2];
    float* out = (float*)d_out;

    cudaFuncSetAttribute(gemm_kernel, cudaFuncAttributeMaxDynamicSharedMemorySize, SMEM_TOTAL);

    normalize_kernel<<<BATCH, 128>>>(emb);
    gemm_kernel<<<NTILES, NTHREADS, SMEM_TOTAL>>>(weight, labels);
    finalize1_kernel<<<BATCH, 256>>>();
    finalize2_kernel<<<1, 256>>>(out);
}

// round 10
// speedup vs baseline: 1.6453x; 1.0289x over previous
#include <cuda_runtime.h>
#include <cuda_fp16.h>
#include <cstdint>

// ============================ problem constants ============================
#define BATCH        256
#define EMBED_DIM    512
#define NUM_CLASSES  100000
#define NUM_SUB      3
#define CK           (NUM_CLASSES * NUM_SUB)   // 300000 weight rows
#define BN           96                         // 32 classes * 3 subcenters
#define CPT          32                         // classes per tile
#define NTILES       (CK / BN)                  // 3125
#define KC           32                         // fp32 k-elems per chunk (128B rows)
#define NCH          (EMBED_DIM / KC)           // 16
#define NTHREADS     384                        // 12 warps: 4M x 3N

#define COS_M  0.87758256189037276f
#define SIN_M  0.47942553860420301f
#define TH_C   (-0.87758256189037276f)
#define MM_C   0.23971276930210150f
#define SCALE_C 64.0f

// SMEM layout (bytes)
#define SM_RNORM 0                   // 96 floats, pad to 512
#define SM_BS    512                 // 4 bufs * 6144 B (96 rows * 64B fp16)
#define SM_AS    25088               // 8 stages * 16384 B (256 rows * 64B fp16)
#define SM_CS    25088               // reuses A region post-mainloop: 256*97*4 = 99328
#define SM_PART  (25088 + 99328)     // 256 floats partial scratch (ends 125440 <= 156160)
#define SMEM_TOTAL (25088 + 8*16384) // 156160

// ============================ PTX helpers ============================
__device__ __forceinline__ uint32_t smem_u32(const void* p) {
    uint32_t a;
    asm("{ .reg .u64 t; cvta.to.shared.u64 t, %1; cvt.u32.u64 %0, t; }" : "=r"(a) : "l"(p));
    return a;
}

__device__ __forceinline__ void ldmatrix_x4(uint32_t* r, uint32_t addr) {
    asm volatile("ldmatrix.sync.aligned.m8n8.x4.shared.b16 {%0,%1,%2,%3}, [%4];"
                 : "=r"(r[0]), "=r"(r[1]), "=r"(r[2]), "=r"(r[3]) : "r"(addr));
}

__device__ __forceinline__ void mma_f16(float* c, const uint32_t* a, const uint32_t* b) {
    asm volatile("mma.sync.aligned.m16n8k16.row.col.f32.f16.f16.f32 "
                 "{%0,%1,%2,%3}, {%4,%5,%6,%7}, {%8,%9}, {%0,%1,%2,%3};"
                 : "+f"(c[0]), "+f"(c[1]), "+f"(c[2]), "+f"(c[3])
                 : "r"(a[0]), "r"(a[1]), "r"(a[2]), "r"(a[3]), "r"(b[0]), "r"(b[1]));
}

#define CP_COMMIT() asm volatile("cp.async.commit_group;" ::: "memory")
#define CP_WAIT1()  asm volatile("cp.async.wait_group 1;" ::: "memory")

// ============================ device scratch ============================
__device__ __align__(128) __half g_A16[BATCH * EMBED_DIM];   // normalized embeddings, fp16
__device__ float g_partial[BATCH * NTILES];                  // [m][tile]
__device__ float g_label[BATCH];

// ============================ kernel 1: normalize embeddings -> fp16 ============================
__global__ void normalize_kernel(const float* __restrict__ e) {
    int r = blockIdx.x, t = threadIdx.x;
    float v[4];
    float s = 0.f;
#pragma unroll
    for (int i = 0; i < 4; i++) { v[i] = e[r * EMBED_DIM + t + i * 128]; s = fmaf(v[i], v[i], s); }
#pragma unroll
    for (int off = 16; off > 0; off >>= 1) s += __shfl_xor_sync(0xFFFFFFFFu, s, off);
    __shared__ float ws[4];
    if ((t & 31) == 0) ws[t >> 5] = s;
    __syncthreads();
    float tot = ws[0] + ws[1] + ws[2] + ws[3];
    float rn = rsqrtf(fmaxf(tot, 1e-24f));
#pragma unroll
    for (int i = 0; i < 4; i++) g_A16[r * EMBED_DIM + t + i * 128] = __float2half_rn(v[i] * rn);
}

// ============================ kernel 2: fused GEMM + ArcFace epilogue ============================
__global__ __launch_bounds__(NTHREADS) void gemm_kernel(
    const float* __restrict__ W, const int* __restrict__ labels)
{
    extern __shared__ char smem[];
    const uint32_t sb = smem_u32(smem);
    const int tid = threadIdx.x;
    const int wid = tid >> 5;
    const int L   = tid & 31;
    const int wm  = wid & 3;      // 0..3 (M blocks of 64)
    const int wn  = wid >> 2;     // 0..2 (N blocks of 32)
    const int tile = blockIdx.x;

    uint64_t gA;
    asm("cvta.to.global.u64 %0, %1;" : "=l"(gA) : "l"((void*)g_A16));

    // ---- B global-load mapping: 2 float4 per thread per chunk ----
    const int brow0 = tid >> 3;   // 0..47
    const int bg    = tid & 7;    // 16B group within 128B chunk-row
    const float* wp0 = W + ((long)tile * BN + brow0) * EMBED_DIM + bg * 4;
    const float* wp1 = W + ((long)tile * BN + brow0 + 48) * EMBED_DIM + bg * 4;

    // ---- precomputed smem addresses (registers) ----
    const uint32_t stsSw  = ((((bg >> 1)) ^ ((brow0 >> 1) & 3)) << 4) + ((bg & 1) << 3);
    const uint32_t stsSw1 = ((((bg >> 1)) ^ (((brow0 + 48) >> 1) & 3)) << 4) + ((bg & 1) << 3);
    const uint32_t sAddr0 = sb + SM_BS + brow0 * 64 + stsSw;
    const uint32_t sAddr1 = sb + SM_BS + (brow0 + 48) * 64 + stsSw1;

    uint32_t aDst[4];
    uint64_t aSrc[4];
    {
        const int r0 = (tid & 255) >> 2, g = tid & 3;
#pragma unroll
        for (int i = 0; i < 4; i++) {
            int r = r0 + i * 64;
            aDst[i] = sb + SM_AS + r * 64 + ((g ^ ((r >> 1) & 3)) << 4);
            aSrc[i] = gA + (uint64_t)(r * EMBED_DIM + g * 8) * 2;
        }
    }

    const int sel = L >> 3, lr = L & 7;
    uint32_t aAddr[4][2], bAddr[2][2];
#pragma unroll
    for (int i = 0; i < 4; i++)
#pragma unroll
        for (int s = 0; s < 2; s++) {
            int row = wm * 64 + i * 16 + ((sel & 1) << 3) + lr;
            int kg  = 2 * s + (sel >> 1);
            aAddr[i][s] = sb + SM_AS + row * 64 + ((kg ^ ((row >> 1) & 3)) << 4);
        }
#pragma unroll
    for (int j0 = 0; j0 < 2; j0++)
#pragma unroll
        for (int s = 0; s < 2; s++) {
            int n  = wn * 32 + (2 * j0 + (sel >> 1)) * 8 + lr;
            int kg = 2 * s + (sel & 1);
            bAddr[j0][s] = sb + SM_BS + n * 64 + ((kg ^ ((n >> 1) & 3)) << 4);
        }

    float4 breg0[2], breg1[2];
    float ss0 = 0.f, ss1 = 0.f;

    auto sts_b = [&](uint32_t addr, const float4 v, float& ss) {
        ss += v.x * v.x + v.y * v.y + v.z * v.z + v.w * v.w;
        __half2 h0 = __floats2half2_rn(v.x, v.y);
        __half2 h1 = __floats2half2_rn(v.z, v.w);
        uint32_t u0 = *reinterpret_cast<uint32_t*>(&h0);
        uint32_t u1 = *reinterpret_cast<uint32_t*>(&h1);
        asm volatile("st.shared.v2.b32 [%0], {%1,%2};" :: "r"(addr), "r"(u0), "r"(u1) : "memory");
    };
    auto cpasync_a = [&](int ch, uint32_t stOff) {
        if (tid < 256) {
            const uint32_t co = (uint32_t)ch * 64;
#pragma unroll
            for (int i = 0; i < 4; i++)
                asm volatile("cp.async.cg.shared.global [%0], [%1], 16;"
                             :: "r"(aDst[i] + stOff), "l"(aSrc[i] + co) : "memory");
        }
    };

    // ---- accumulators ----
    float c[4][4][4];
#pragma unroll
    for (int i = 0; i < 4; i++)
#pragma unroll
        for (int j = 0; j < 4; j++)
#pragma unroll
            for (int q = 0; q < 4; q++) c[i][j][q] = 0.f;

    // ---- prologue: B chunks 0,1 -> bufs 0,1; LDG chunks 2,3; A pairs (0,1) + (2,3) ----
    {
        float4 t0 = *reinterpret_cast<const float4*>(wp0);
        float4 t1 = *reinterpret_cast<const float4*>(wp1);
        float4 t2 = *reinterpret_cast<const float4*>(wp0 + KC);
        float4 t3 = *reinterpret_cast<const float4*>(wp1 + KC);
        sts_b(sAddr0, t0, ss0);
        sts_b(sAddr1, t1, ss1);
        sts_b(sAddr0 + 6144, t2, ss0);
        sts_b(sAddr1 + 6144, t3, ss1);
        breg0[0] = *reinterpret_cast<const float4*>(wp0 + 2 * KC);
        breg1[0] = *reinterpret_cast<const float4*>(wp1 + 2 * KC);
        breg0[1] = *reinterpret_cast<const float4*>(wp0 + 3 * KC);
        breg1[1] = *reinterpret_cast<const float4*>(wp1 + 3 * KC);
        cpasync_a(0, 0);
        cpasync_a(1, 16384);
        CP_COMMIT();                 // group = pair (0,1)
        cpasync_a(2, 32768);
        cpasync_a(3, 49152);
        CP_COMMIT();                 // group = pair (2,3)
    }

    // ---- mainloop: 8 chunk-pairs; one wait + one barrier per pair ----
#pragma unroll 1
    for (int t = 0; t < 2; t++) {
#pragma unroll
        for (int jp = 0; jp < 4; jp++) {
            const int p  = t * 4 + jp;    // pair index 0..7
            const int k0 = 2 * p;         // chunks k0, k0+1
            CP_WAIT1();                   // pair p's A complete (this thread)
            __syncthreads();              // A(pair p) + B(chunks k0,k0+1) visible to all
            // STS B chunks k0+2, k0+3 (consumed only after the NEXT pair's barrier)
            if (p <= 6) {
                sts_b(sAddr0 + (uint32_t)((k0 + 2) & 3) * 6144, breg0[0], ss0);
                sts_b(sAddr1 + (uint32_t)((k0 + 2) & 3) * 6144, breg1[0], ss1);
                sts_b(sAddr0 + (uint32_t)((k0 + 3) & 3) * 6144, breg0[1], ss0);
                sts_b(sAddr1 + (uint32_t)((k0 + 3) & 3) * 6144, breg1[1], ss1);
            }
            if (p <= 5) {
                // LDG B chunks k0+4, k0+5
                breg0[0] = *reinterpret_cast<const float4*>(wp0 + (k0 + 4) * KC);
                breg1[0] = *reinterpret_cast<const float4*>(wp1 + (k0 + 4) * KC);
                breg0[1] = *reinterpret_cast<const float4*>(wp0 + (k0 + 5) * KC);
                breg1[1] = *reinterpret_cast<const float4*>(wp1 + (k0 + 5) * KC);
                // A pair (k0+4, k0+5) into stages (k0+4)&7, (k0+5)&7
                cpasync_a(k0 + 4, (uint32_t)((k0 + 4) & 7) * 16384);
                cpasync_a(k0 + 5, (uint32_t)((k0 + 5) & 7) * 16384);
            }
            CP_COMMIT();
            // ---- compute chunks k0, k0+1 ----
#pragma unroll
            for (int cc = 0; cc < 2; cc++) {
                const uint32_t aOff = (uint32_t)((k0 + cc) & 7) * 16384;
                const uint32_t bOff = (uint32_t)((k0 + cc) & 3) * 6144;
#pragma unroll
                for (int s = 0; s < 2; s++) {
                    uint32_t a[4][4];
#pragma unroll
                    for (int i = 0; i < 4; i++) ldmatrix_x4(a[i], aAddr[i][s] + aOff);
                    uint32_t b[4][2];
#pragma unroll
                    for (int j0 = 0; j0 < 2; j0++) {
                        uint32_t r[4];
                        ldmatrix_x4(r, bAddr[j0][s] + bOff);
                        b[2 * j0][0] = r[0]; b[2 * j0][1] = r[1];
                        b[2 * j0 + 1][0] = r[2]; b[2 * j0 + 1][1] = r[3];
                    }
#pragma unroll
                    for (int i = 0; i < 4; i++)
#pragma unroll
                        for (int j = 0; j < 4; j++) mma_f16(c[i][j], a[i], b[j]);
                }
            }
        }
    }

    // ---- weight-row rnorm (from conversion-time sumsq) ----
#pragma unroll
    for (int o = 1; o < 8; o <<= 1) {
        ss0 += __shfl_xor_sync(0xFFFFFFFFu, ss0, o);
        ss1 += __shfl_xor_sync(0xFFFFFFFFu, ss1, o);
    }
    float* rn = reinterpret_cast<float*>(smem + SM_RNORM);
    if ((L & 7) == 0) {
        rn[brow0]      = rsqrtf(fmaxf(ss0, 1e-24f));
        rn[brow0 + 48] = rsqrtf(fmaxf(ss1, 1e-24f));
    }
    __syncthreads();

    // ---- epilogue: single staged pass (full 256x97 Cs in freed A region) ----
    // All __syncthreads below are UNIFORM.
    const int class0 = tile * CPT;
    float* Cs = reinterpret_cast<float*>(smem + SM_CS);
    float* PartS = reinterpret_cast<float*>(smem + SM_PART);
    {
        const int mr0 = wm * 64;
#pragma unroll
        for (int i = 0; i < 4; i++) {
            int r = mr0 + i * 16 + (L >> 2);
#pragma unroll
            for (int j = 0; j < 4; j++) {
                int col = wn * 32 + j * 8 + 2 * (L & 3);
                float s0 = rn[col], s1 = rn[col + 1];
                Cs[r * 97 + col]           = c[i][j][0] * s0;
                Cs[r * 97 + col + 1]       = c[i][j][1] * s1;
                Cs[(r + 8) * 97 + col]     = c[i][j][2] * s0;
                Cs[(r + 8) * 97 + col + 1] = c[i][j][3] * s1;
            }
        }
    }
    __syncthreads();                           // full Cs staged

    float sg[2] = {0.f, 0.f};
    int row = 0, part = 0;
    if (tid < 256) {
        row  = tid >> 1;                       // 0..127
        part = tid & 1;                        // classes [16*part, 16*part+16)
        const int cbeg = part * 16;
#pragma unroll 1
        for (int g = 0; g < 2; g++) {
            const int m = g * 128 + row;
            const int labloc = labels[m] - class0;   // in [0,32) iff label here
            const float* rowp = Cs + m * 97;
            float sum = 0.f;
#pragma unroll 4
            for (int cc = cbeg; cc < cbeg + 16; cc++) {
                float v0 = rowp[3 * cc], v1 = rowp[3 * cc + 1], v2 = rowp[3 * cc + 2];
                float cosv = fmaxf(v0, fmaxf(v1, v2));
                float val = cosv;
                if (cc == labloc) {
                    float sine = sqrtf(fmaxf(1.f - cosv * cosv, 0.f));
                    float phi = cosv * COS_M - sine * SIN_M;
                    phi = (cosv > TH_C) ? phi : (cosv - MM_C);
                    val = phi;
                    g_label[m] = SCALE_C * phi;
                }
                sum += __expf(SCALE_C * (val - 1.f));
            }
            sg[g] = sum;
            if (part) PartS[m] = sum;
        }
    }
    __syncthreads();                           // PartS visible
    if (tid < 256 && !part) {
        g_partial[(long)row * NTILES + tile]         = sg[0] + PartS[row];
        g_partial[(long)(row + 128) * NTILES + tile] = sg[1] + PartS[row + 128];
    }
}

// ============================ kernel 3: finalize (fused reduce + mean) ============================
__global__ void finalize_kernel(float* __restrict__ out) {
    const int m = blockIdx.x;
    const int t = threadIdx.x;   // 256 threads
    const float* row = g_partial + (long)m * NTILES;
    float s = 0.f;
    for (int i = t; i < NTILES; i += 256) s += row[i];
#pragma unroll
    for (int off = 16; off > 0; off >>= 1) s += __shfl_xor_sync(0xFFFFFFFFu, s, off);
    __shared__ float ws[8];
    if ((t & 31) == 0) ws[t >> 5] = s;
    __syncthreads();
    if (t == 0) {
        float tot = 0.f;
#pragma unroll
        for (int i = 0; i < 8; i++) tot += ws[i];
        float loss = SCALE_C + logf(tot) - g_label[m];
        atomicAdd(out, loss * (1.0f / 256.0f));
    }
}

// ============================ host launch ============================
extern "C" void kernel_launch(void* const* d_in, const int* in_sizes, int n_in,
                              void* d_out, int out_size) {
    const float* emb    = (const float*)d_in[0];
    const int*   labels = (const int*)d_in[1];    // JAX w/o x64: int64 randint -> int32
    const float* weight = (const float*)d_in[2];
    float* out = (float*)d_out;

    cudaFuncSetAttribute(gemm_kernel, cudaFuncAttributeMaxDynamicSharedMemorySize, SMEM_TOTAL);

    cudaMemsetAsync(d_out, 0, sizeof(float));
    normalize_kernel<<<BATCH, 128>>>(emb);
    gemm_kernel<<<NTILES, NTHREADS, SMEM_TOTAL>>>(weight, labels);
    finalize_kernel<<<BATCH, 256>>>(out);
}

// round 12
// speedup vs baseline: 1.6731x; 1.0169x over previous
#include <cuda_runtime.h>
#include <cuda_fp16.h>
#include <cstdint>

// ============================ problem constants ============================
#define BATCH        256
#define EMBED_DIM    512
#define NUM_CLASSES  100000
#define NUM_SUB      3
#define CK           (NUM_CLASSES * NUM_SUB)   // 300000 weight rows
#define BN           96                         // 32 classes * 3 subcenters
#define CPT          32                         // classes per tile
#define NTILES       (CK / BN)                  // 3125
#define KC           32                         // fp32 k-elems per chunk (128B rows)
#define NCH          (EMBED_DIM / KC)           // 16
#define NTHREADS     384                        // 12 warps: 4M x 3N

#define COS_M  0.87758256189037276f
#define SIN_M  0.47942553860420301f
#define TH_C   (-0.87758256189037276f)
#define MM_C   0.23971276930210150f
#define SCALE_C 64.0f

// SMEM layout (bytes)
#define SM_RNORM 0                   // 96 floats, pad to 512
#define SM_BS    512                 // 8 bufs * 6144 B (96 rows * 64B fp16)
#define SM_AS    49664               // 8 stages * 16384 B (256 rows * 64B fp16)
#define SM_CS    49664               // reuses A region post-mainloop: 256*97*4 = 99328
#define SMEM_TOTAL (49664 + 8*16384) // 180736

// ============================ PTX helpers ============================
__device__ __forceinline__ uint32_t smem_u32(const void* p) {
    uint32_t a;
    asm("{ .reg .u64 t; cvta.to.shared.u64 t, %1; cvt.u32.u64 %0, t; }" : "=r"(a) : "l"(p));
    return a;
}

__device__ __forceinline__ void ldmatrix_x4(uint32_t* r, uint32_t addr) {
    asm volatile("ldmatrix.sync.aligned.m8n8.x4.shared.b16 {%0,%1,%2,%3}, [%4];"
                 : "=r"(r[0]), "=r"(r[1]), "=r"(r[2]), "=r"(r[3]) : "r"(addr));
}

__device__ __forceinline__ void mma_f16(float* c, const uint32_t* a, const uint32_t* b) {
    asm volatile("mma.sync.aligned.m16n8k16.row.col.f32.f16.f16.f32 "
                 "{%0,%1,%2,%3}, {%4,%5,%6,%7}, {%8,%9}, {%0,%1,%2,%3};"
                 : "+f"(c[0]), "+f"(c[1]), "+f"(c[2]), "+f"(c[3])
                 : "r"(a[0]), "r"(a[1]), "r"(a[2]), "r"(a[3]), "r"(b[0]), "r"(b[1]));
}

#define CP_COMMIT() asm volatile("cp.async.commit_group;" ::: "memory")
#define CP_WAIT0()  asm volatile("cp.async.wait_group 0;" ::: "memory")

// ============================ device scratch ============================
__device__ __align__(128) __half g_A16[BATCH * EMBED_DIM];   // normalized embeddings, fp16
__device__ float g_rowsum[BATCH];                            // atomically accumulated exp-sums
__device__ float g_label[BATCH];

// ============================ kernel 1: normalize embeddings -> fp16 (+zero rowsum) ============================
__global__ void normalize_kernel(const float* __restrict__ e) {
    int r = blockIdx.x, t = threadIdx.x;
    if (t == 0) g_rowsum[r] = 0.f;
    float v[4];
    float s = 0.f;
#pragma unroll
    for (int i = 0; i < 4; i++) { v[i] = e[r * EMBED_DIM + t + i * 128]; s = fmaf(v[i], v[i], s); }
#pragma unroll
    for (int off = 16; off > 0; off >>= 1) s += __shfl_xor_sync(0xFFFFFFFFu, s, off);
    __shared__ float ws[4];
    if ((t & 31) == 0) ws[t >> 5] = s;
    __syncthreads();
    float tot = ws[0] + ws[1] + ws[2] + ws[3];
    float rn = rsqrtf(fmaxf(tot, 1e-24f));
#pragma unroll
    for (int i = 0; i < 4; i++) g_A16[r * EMBED_DIM + t + i * 128] = __float2half_rn(v[i] * rn);
}

// ============================ kernel 2: fused GEMM + ArcFace epilogue ============================
__global__ __launch_bounds__(NTHREADS) void gemm_kernel(
    const float* __restrict__ W, const int* __restrict__ labels)
{
    extern __shared__ char smem[];
    const uint32_t sb = smem_u32(smem);
    const int tid = threadIdx.x;
    const int wid = tid >> 5;
    const int L   = tid & 31;
    const int wm  = wid & 3;      // 0..3 (M blocks of 64)
    const int wn  = wid >> 2;     // 0..2 (N blocks of 32)
    const int tile = blockIdx.x;

    uint64_t gA;
    asm("cvta.to.global.u64 %0, %1;" : "=l"(gA) : "l"((void*)g_A16));

    // ---- B global-load mapping: 2 float4 per thread per chunk ----
    const int brow0 = tid >> 3;   // 0..47
    const int bg    = tid & 7;    // 16B group within 128B chunk-row
    const float* wp0 = W + ((long)tile * BN + brow0) * EMBED_DIM + bg * 4;
    const float* wp1 = W + ((long)tile * BN + brow0 + 48) * EMBED_DIM + bg * 4;

    // ---- precomputed smem addresses ----
    const uint32_t stsSw  = ((((bg >> 1)) ^ ((brow0 >> 1) & 3)) << 4) + ((bg & 1) << 3);
    const uint32_t stsSw1 = ((((bg >> 1)) ^ (((brow0 + 48) >> 1) & 3)) << 4) + ((bg & 1) << 3);
    const uint32_t sAddr0 = sb + SM_BS + brow0 * 64 + stsSw;
    const uint32_t sAddr1 = sb + SM_BS + (brow0 + 48) * 64 + stsSw1;

    uint32_t aDst[4];
    uint64_t aSrc[4];
    {
        const int r0 = (tid & 255) >> 2, g = tid & 3;
#pragma unroll
        for (int i = 0; i < 4; i++) {
            int r = r0 + i * 64;
            aDst[i] = sb + SM_AS + r * 64 + ((g ^ ((r >> 1) & 3)) << 4);
            aSrc[i] = gA + (uint64_t)(r * EMBED_DIM + g * 8) * 2;
        }
    }

    const int sel = L >> 3, lr = L & 7;
    uint32_t aAddr[4][2], bAddr[2][2];
#pragma unroll
    for (int i = 0; i < 4; i++)
#pragma unroll
        for (int s = 0; s < 2; s++) {
            int row = wm * 64 + i * 16 + ((sel & 1) << 3) + lr;
            int kg  = 2 * s + (sel >> 1);
            aAddr[i][s] = sb + SM_AS + row * 64 + ((kg ^ ((row >> 1) & 3)) << 4);
        }
#pragma unroll
    for (int j0 = 0; j0 < 2; j0++)
#pragma unroll
        for (int s = 0; s < 2; s++) {
            int n  = wn * 32 + (2 * j0 + (sel >> 1)) * 8 + lr;
            int kg = 2 * s + (sel & 1);
            bAddr[j0][s] = sb + SM_BS + n * 64 + ((kg ^ ((n >> 1) & 3)) << 4);
        }

    float4 breg0[2], breg1[2];
    float ss0 = 0.f, ss1 = 0.f;

    auto sts_b = [&](uint32_t addr, const float4 v, float& ss) {
        ss += v.x * v.x + v.y * v.y + v.z * v.z + v.w * v.w;
        __half2 h0 = __floats2half2_rn(v.x, v.y);
        __half2 h1 = __floats2half2_rn(v.z, v.w);
        uint32_t u0 = *reinterpret_cast<uint32_t*>(&h0);
        uint32_t u1 = *reinterpret_cast<uint32_t*>(&h1);
        asm volatile("st.shared.v2.b32 [%0], {%1,%2};" :: "r"(addr), "r"(u0), "r"(u1) : "memory");
    };
    auto cpasync_a = [&](int ch, uint32_t stOff) {
        if (tid < 256) {
            const uint32_t co = (uint32_t)ch * 64;
#pragma unroll
            for (int i = 0; i < 4; i++)
                asm volatile("cp.async.cg.shared.global [%0], [%1], 16;"
                             :: "r"(aDst[i] + stOff), "l"(aSrc[i] + co) : "memory");
        }
    };

    // ---- accumulators ----
    float c[4][4][4];
#pragma unroll
    for (int i = 0; i < 4; i++)
#pragma unroll
        for (int j = 0; j < 4; j++)
#pragma unroll
            for (int q = 0; q < 4; q++) c[i][j][q] = 0.f;

    // ---- prologue: B chunks 0-3 -> bufs 0-3; B chunks 4,5 -> regs; A quad 0 ----
    {
        float4 t0 = *reinterpret_cast<const float4*>(wp0);
        float4 t1 = *reinterpret_cast<const float4*>(wp1);
        float4 t2 = *reinterpret_cast<const float4*>(wp0 + KC);
        float4 t3 = *reinterpret_cast<const float4*>(wp1 + KC);
        sts_b(sAddr0, t0, ss0);
        sts_b(sAddr1, t1, ss1);
        sts_b(sAddr0 + 1 * 6144, t2, ss0);
        sts_b(sAddr1 + 1 * 6144, t3, ss1);
        breg0[0] = *reinterpret_cast<const float4*>(wp0 + 2 * KC);
        breg1[0] = *reinterpret_cast<const float4*>(wp1 + 2 * KC);
        breg0[1] = *reinterpret_cast<const float4*>(wp0 + 3 * KC);
        breg1[1] = *reinterpret_cast<const float4*>(wp1 + 3 * KC);
        sts_b(sAddr0 + 2 * 6144, breg0[0], ss0);
        sts_b(sAddr1 + 2 * 6144, breg1[0], ss1);
        sts_b(sAddr0 + 3 * 6144, breg0[1], ss0);
        sts_b(sAddr1 + 3 * 6144, breg1[1], ss1);
        breg0[0] = *reinterpret_cast<const float4*>(wp0 + 4 * KC);
        breg1[0] = *reinterpret_cast<const float4*>(wp1 + 4 * KC);
        breg0[1] = *reinterpret_cast<const float4*>(wp0 + 5 * KC);
        breg1[1] = *reinterpret_cast<const float4*>(wp1 + 5 * KC);
        cpasync_a(0, 0);
        cpasync_a(1, 1 * 16384);
        cpasync_a(2, 2 * 16384);
        cpasync_a(3, 3 * 16384);
        CP_COMMIT();                 // group = quad 0 (A is L2-hot; ready fast)
    }

    // ---- mainloop: 4 quads; one wait + one barrier per quad ----
#pragma unroll 1
    for (int q = 0; q < 4; q++) {
        const int k0 = 4 * q;
        CP_WAIT0();                   // quad q's A complete (this thread)
        __syncthreads();              // quad q A+B visible to all; prior quad's stages free
        // A quad q+1 into the set just freed (stages (k0+4)&7 .. (k0+7)&7)
        if (q <= 2) {
            cpasync_a(k0 + 4, (uint32_t)((k0 + 4) & 7) * 16384);
            cpasync_a(k0 + 5, (uint32_t)((k0 + 5) & 7) * 16384);
            cpasync_a(k0 + 6, (uint32_t)((k0 + 6) & 7) * 16384);
            cpasync_a(k0 + 7, (uint32_t)((k0 + 7) & 7) * 16384);
            // STS B chunks k0+4, k0+5 (bufs freed last quad; visible via next barrier)
            sts_b(sAddr0 + (uint32_t)((k0 + 4) & 7) * 6144, breg0[0], ss0);
            sts_b(sAddr1 + (uint32_t)((k0 + 4) & 7) * 6144, breg1[0], ss1);
            sts_b(sAddr0 + (uint32_t)((k0 + 5) & 7) * 6144, breg0[1], ss0);
            sts_b(sAddr1 + (uint32_t)((k0 + 5) & 7) * 6144, breg1[1], ss1);
            // LDG B chunks k0+6, k0+7
            breg0[0] = *reinterpret_cast<const float4*>(wp0 + (k0 + 6) * KC);
            breg1[0] = *reinterpret_cast<const float4*>(wp1 + (k0 + 6) * KC);
            breg0[1] = *reinterpret_cast<const float4*>(wp0 + (k0 + 7) * KC);
            breg1[1] = *reinterpret_cast<const float4*>(wp1 + (k0 + 7) * KC);
        }
        CP_COMMIT();                  // (empty for q=3: keeps FIFO accounting uniform)
        // ---- compute chunks k0, k0+1 ----
#pragma unroll
        for (int cc = 0; cc < 2; cc++) {
            const uint32_t aOff = (uint32_t)((k0 + cc) & 7) * 16384;
            const uint32_t bOff = (uint32_t)((k0 + cc) & 7) * 6144;
#pragma unroll
            for (int s = 0; s < 2; s++) {
                uint32_t a[4][4];
#pragma unroll
                for (int i = 0; i < 4; i++) ldmatrix_x4(a[i], aAddr[i][s] + aOff);
                uint32_t b[4][2];
#pragma unroll
                for (int j0 = 0; j0 < 2; j0++) {
                    uint32_t r[4];
                    ldmatrix_x4(r, bAddr[j0][s] + bOff);
                    b[2 * j0][0] = r[0]; b[2 * j0][1] = r[1];
                    b[2 * j0 + 1][0] = r[2]; b[2 * j0 + 1][1] = r[3];
                }
#pragma unroll
                for (int i = 0; i < 4; i++)
#pragma unroll
                    for (int j = 0; j < 4; j++) mma_f16(c[i][j], a[i], b[j]);
            }
        }
        // STS B chunks k0+6,k0+7 (LDG'd above; 2-chunk compute covered latency); LDG k0+8,k0+9
        if (q <= 2) {
            sts_b(sAddr0 + (uint32_t)((k0 + 6) & 7) * 6144, breg0[0], ss0);
            sts_b(sAddr1 + (uint32_t)((k0 + 6) & 7) * 6144, breg1[0], ss1);
            sts_b(sAddr0 + (uint32_t)((k0 + 7) & 7) * 6144, breg0[1], ss0);
            sts_b(sAddr1 + (uint32_t)((k0 + 7) & 7) * 6144, breg1[1], ss1);
        }
        if (q <= 1) {
            breg0[0] = *reinterpret_cast<const float4*>(wp0 + (k0 + 8) * KC);
            breg1[0] = *reinterpret_cast<const float4*>(wp1 + (k0 + 8) * KC);
            breg0[1] = *reinterpret_cast<const float4*>(wp0 + (k0 + 9) * KC);
            breg1[1] = *reinterpret_cast<const float4*>(wp1 + (k0 + 9) * KC);
        }
        // ---- compute chunks k0+2, k0+3 ----
#pragma unroll
        for (int cc = 2; cc < 4; cc++) {
            const uint32_t aOff = (uint32_t)((k0 + cc) & 7) * 16384;
            const uint32_t bOff = (uint32_t)((k0 + cc) & 7) * 6144;
#pragma unroll
            for (int s = 0; s < 2; s++) {
                uint32_t a[4][4];
#pragma unroll
                for (int i = 0; i < 4; i++) ldmatrix_x4(a[i], aAddr[i][s] + aOff);
                uint32_t b[4][2];
#pragma unroll
                for (int j0 = 0; j0 < 2; j0++) {
                    uint32_t r[4];
                    ldmatrix_x4(r, bAddr[j0][s] + bOff);
                    b[2 * j0][0] = r[0]; b[2 * j0][1] = r[1];
                    b[2 * j0 + 1][0] = r[2]; b[2 * j0 + 1][1] = r[3];
                }
#pragma unroll
                for (int i = 0; i < 4; i++)
#pragma unroll
                    for (int j = 0; j < 4; j++) mma_f16(c[i][j], a[i], b[j]);
            }
        }
    }

    // ---- weight-row rnorm (from conversion-time sumsq) ----
#pragma unroll
    for (int o = 1; o < 8; o <<= 1) {
        ss0 += __shfl_xor_sync(0xFFFFFFFFu, ss0, o);
        ss1 += __shfl_xor_sync(0xFFFFFFFFu, ss1, o);
    }
    float* rn = reinterpret_cast<float*>(smem + SM_RNORM);
    if ((L & 7) == 0) {
        rn[brow0]      = rsqrtf(fmaxf(ss0, 1e-24f));
        rn[brow0 + 48] = rsqrtf(fmaxf(ss1, 1e-24f));
    }
    __syncthreads();

    // ---- epilogue: single staged pass (full 256x97 Cs in freed A region) ----
    const int class0 = tile * CPT;
    float* Cs = reinterpret_cast<float*>(smem + SM_CS);
    {
        const int mr0 = wm * 64;
#pragma unroll
        for (int i = 0; i < 4; i++) {
            int r = mr0 + i * 16 + (L >> 2);
#pragma unroll
            for (int j = 0; j < 4; j++) {
                int col = wn * 32 + j * 8 + 2 * (L & 3);
                float s0 = rn[col], s1 = rn[col + 1];
                Cs[r * 97 + col]           = c[i][j][0] * s0;
                Cs[r * 97 + col + 1]       = c[i][j][1] * s1;
                Cs[(r + 8) * 97 + col]     = c[i][j][2] * s0;
                Cs[(r + 8) * 97 + col + 1] = c[i][j][3] * s1;
            }
        }
    }
    __syncthreads();                           // full Cs staged

    if (tid < 256) {
        const int row  = tid >> 1;             // 0..127
        const int part = tid & 1;              // classes [16*part, 16*part+16)
        const int cbeg = part * 16;
#pragma unroll 1
        for (int g = 0; g < 2; g++) {
            const int m = g * 128 + row;
            const int labloc = labels[m] - class0;   // in [0,32) iff label here
            const float* rowp = Cs + m * 97;
            float sum = 0.f;
#pragma unroll 4
            for (int cc = cbeg; cc < cbeg + 16; cc++) {
                float v0 = rowp[3 * cc], v1 = rowp[3 * cc + 1], v2 = rowp[3 * cc + 2];
                float cosv = fmaxf(v0, fmaxf(v1, v2));
                float val = cosv;
                if (cc == labloc) {
                    float sine = sqrtf(fmaxf(1.f - cosv * cosv, 0.f));
                    float phi = cosv * COS_M - sine * SIN_M;
                    phi = (cosv > TH_C) ? phi : (cosv - MM_C);
                    val = phi;
                    g_label[m] = SCALE_C * phi;
                }
                sum += __expf(SCALE_C * (val - 1.f));
            }
            atomicAdd(&g_rowsum[m], sum);      // REDG, spread addresses
        }
    }
}

// ============================ kernel 3: finalize (tiny) ============================
__global__ void finalize_kernel(float* __restrict__ out) {
    const int m = threadIdx.x;   // 256 threads
    float loss = SCALE_C + logf(g_rowsum[m]) - g_label[m];
#pragma unroll
    for (int off = 16; off > 0; off >>= 1) loss += __shfl_xor_sync(0xFFFFFFFFu, loss, off);
    __shared__ float ws[8];
    if ((m & 31) == 0) ws[m >> 5] = loss;
    __syncthreads();
    if (m == 0) {
        float tot = 0.f;
#pragma unroll
        for (int i = 0; i < 8; i++) tot += ws[i];
        out[0] = tot * (1.0f / 256.0f);
    }
}

// ============================ host launch ============================
extern "C" void kernel_launch(void* const* d_in, const int* in_sizes, int n_in,
                              void* d_out, int out_size) {
    const float* emb    = (const float*)d_in[0];
    const int*   labels = (const int*)d_in[1];    // JAX w/o x64: int64 randint -> int32
    const float* weight = (const float*)d_in[2];
    float* out = (float*)d_out;

    cudaFuncSetAttribute(gemm_kernel, cudaFuncAttributeMaxDynamicSharedMemorySize, SMEM_TOTAL);

    normalize_kernel<<<BATCH, 128>>>(emb);
    gemm_kernel<<<NTILES, NTHREADS, SMEM_TOTAL>>>(weight, labels);
    finalize_kernel<<<1, 256>>>(out);
}